// round 11
// baseline (speedup 1.0000x reference)
#include <cuda_runtime.h>
#include <cuda_bf16.h>
#include <cstdint>

namespace {
constexpr int B_ = 128, U_ = 64, A_ = 64, C_ = 64, NPOS = 4096;
constexpr float INV63 = 1.0f / 63.0f;
constexpr float INV3969 = (1.0f / 63.0f) * (1.0f / 63.0f);
}

// ---- persistent scratch (no cudaMalloc allowed) ----
#define PLANE_SZ ((size_t)B_ * NPOS * C_)
__device__ __nv_bfloat16 P_h_hi[PLANE_SZ], P_h_lo[PLANE_SZ];
__device__ __nv_bfloat16 P_m_hi[PLANE_SZ], P_m_lo[PLANE_SZ];
__device__ __nv_bfloat16 P_s_hi[PLANE_SZ], P_s_lo[PLANE_SZ];
__device__ float g_colU_h[B_ * C_ * A_];
__device__ float g_colU_m[B_ * C_ * A_];
__device__ float g_colU_s[B_ * C_ * A_];
__device__ float g_rowA[B_ * C_ * U_];
__device__ float g_T[B_ * C_];

// ---- helpers ----
__device__ __forceinline__ uint32_t smem_u32(const void* p) {
    uint32_t a;
    asm("{ .reg .u64 t; cvta.to.shared.u64 t, %1; cvt.u32.u64 %0, t; }" : "=r"(a) : "l"(p));
    return a;
}
__device__ __forceinline__ uint32_t sw128(uint32_t off) { return off ^ ((off >> 3) & 0x70); }

#define CP_ASYNC16(d, s)  asm volatile("cp.async.cg.shared.global [%0], [%1], 16;" :: "r"(d), "l"(s) : "memory")
#define CP_COMMIT()       asm volatile("cp.async.commit_group;" ::: "memory")
#define CP_WAIT(n)        asm volatile("cp.async.wait_group %0;" :: "n"(n) : "memory")

#define LDSM4(r, addr) \
    asm volatile("ldmatrix.sync.aligned.m8n8.x4.shared.b16 {%0,%1,%2,%3}, [%4];" \
        : "=r"((r)[0]), "=r"((r)[1]), "=r"((r)[2]), "=r"((r)[3]) : "r"(addr))
#define LDSM2(r0, r1, addr) \
    asm volatile("ldmatrix.sync.aligned.m8n8.x2.shared.b16 {%0,%1}, [%2];" \
        : "=r"(r0), "=r"(r1) : "r"(addr))

__device__ __forceinline__ void mma_bf16(float* d, const uint32_t* a, uint32_t b0, uint32_t b1) {
    asm volatile(
        "mma.sync.aligned.m16n8k16.row.col.f32.bf16.bf16.f32 "
        "{%0,%1,%2,%3}, {%4,%5,%6,%7}, {%8,%9}, {%0,%1,%2,%3};"
        : "+f"(d[0]), "+f"(d[1]), "+f"(d[2]), "+f"(d[3])
        : "r"(a[0]), "r"(a[1]), "r"(a[2]), "r"(a[3]), "r"(b0), "r"(b1));
}

enum Lv { L_PHI1, L_PHIK1, L_PHI2, L_GAMMA1, L_GAMMA2, L_GAMMAK1 };

template<int V> struct Cfg;
template<> struct Cfg<L_PHI1>    { static constexpr int NCH=0, CIN=2;   static constexpr bool RELU=1, TRANS=0, AGG=0, CG=1, ROWA=0; };
template<> struct Cfg<L_PHIK1>   { static constexpr int NCH=1, CIN=65;  static constexpr bool RELU=1, TRANS=1, AGG=0, CG=1, ROWA=0; };
template<> struct Cfg<L_PHI2>    { static constexpr int NCH=1, CIN=64;  static constexpr bool RELU=0, TRANS=1, AGG=0, CG=0, ROWA=1; };
template<> struct Cfg<L_GAMMA1>  { static constexpr int NCH=1, CIN=65;  static constexpr bool RELU=1, TRANS=0, AGG=1, CG=1, ROWA=0; };
template<> struct Cfg<L_GAMMA2>  { static constexpr int NCH=1, CIN=64;  static constexpr bool RELU=1, TRANS=1, AGG=0, CG=0, ROWA=0; };
template<> struct Cfg<L_GAMMAK1> { static constexpr int NCH=2, CIN=128; static constexpr bool RELU=1, TRANS=1, AGG=1, CG=0, ROWA=0; };

// SMEM layout (dynamic): XB double buffer (2 x [hi16K|lo16K]) | W (NCH x [hi8K|lo8K]) |
// STG 128x66 f32 | BA 64x32 | BU 64x64 | CU 64x32 | WCG 64 | BV 64
constexpr int OFF_XB = 0;
constexpr int XBUF_B = 32768;
constexpr int OFF_W  = OFF_XB + 2 * XBUF_B;            // 65536
constexpr int STG_STRIDE = 66;
__host__ __device__ constexpr int smem_off_st(int nch)  { return OFF_W + nch * 16384; }
__host__ __device__ constexpr int smem_off_ba(int nch)  { return smem_off_st(nch) + 128 * STG_STRIDE * 4; }
__host__ __device__ constexpr int smem_off_bu(int nch)  { return smem_off_ba(nch) + 8192; }
__host__ __device__ constexpr int smem_off_cu(int nch)  { return smem_off_bu(nch) + 16384; }
__host__ __device__ constexpr int smem_off_wcg(int nch) { return smem_off_cu(nch) + 8192; }
__host__ __device__ constexpr int smem_off_bv(int nch)  { return smem_off_wcg(nch) + 256; }
__host__ __device__ constexpr int smem_bytes(int nch)   { return smem_off_bv(nch) + 256; }

template<int V>
__global__ __launch_bounds__(128, 1)
void layer_kernel(const float* __restrict__ cgp,
                  const float* __restrict__ Wg,
                  const float* __restrict__ bg)
{
    using CF = Cfg<V>;
    constexpr int NCH = CF::NCH;
    extern __shared__ char sm[];
    const uint32_t smb = smem_u32(sm);
    const int tid = threadIdx.x, wid = tid >> 5, lane = tid & 31;
    const int half = blockIdx.x, b = blockIdx.y;

    float* STG_s = (float*)(sm + smem_off_st(NCH));
    float* BA_s  = (float*)(sm + smem_off_ba(NCH));
    float* BU_s  = (float*)(sm + smem_off_bu(NCH));
    float* CU_s  = (float*)(sm + smem_off_cu(NCH));
    float* WCG_s = (float*)(sm + smem_off_wcg(NCH));
    float* BV_s  = (float*)(sm + smem_off_bv(NCH));

    // plane selection
    const __nv_bfloat16* inH[2] = {nullptr, nullptr};
    const __nv_bfloat16* inL[2] = {nullptr, nullptr};
    if constexpr (V == L_PHIK1)  { inH[0] = P_s_hi; inL[0] = P_s_lo; }
    if constexpr (V == L_PHI2 || V == L_GAMMA2) { inH[0] = P_h_hi; inL[0] = P_h_lo; }
    if constexpr (V == L_GAMMA1) { inH[0] = P_m_hi; inL[0] = P_m_lo; }
    if constexpr (V == L_GAMMAK1){ inH[0] = P_s_hi; inL[0] = P_s_lo; inH[1] = P_m_hi; inL[1] = P_m_lo; }
    __nv_bfloat16 *outH, *outL; float* colUout;
    if constexpr (V == L_PHI2)       { outH = P_m_hi; outL = P_m_lo; colUout = g_colU_m; }
    else if constexpr (V == L_GAMMA2){ outH = P_s_hi; outL = P_s_lo; colUout = g_colU_s; }
    else                             { outH = P_h_hi; outL = P_h_lo; colUout = g_colU_h; }

    // ---- prologue: folded weights (bf16 hi/lo, rows=n 128B, sw128) ----
    auto wfold = [&](int ch, int o, int c) -> float {
        float w, f;
        if constexpr (V == L_PHIK1)      { w = Wg[o * CF::CIN + 1 + c]; f = (c < 32) ? 1.f : -INV63; }
        else if constexpr (V == L_PHI2 || V == L_GAMMA2) { w = Wg[o * CF::CIN + c]; f = (c < 32) ? 1.f : -INV63; }
        else if constexpr (V == L_GAMMA1){ w = Wg[o * CF::CIN + 1 + c]; f = (c < 32) ? -INV63 : INV3969; }
        else { // GAMMAK1
            if (ch == 0) { w = Wg[o * CF::CIN + c];      f = (c < 32) ? 1.f : -INV63; }
            else         { w = Wg[o * CF::CIN + 64 + c]; f = (c < 32) ? -INV63 : INV3969; }
        }
        return w * f;
    };
    if constexpr (NCH > 0) {
        for (int ch = 0; ch < NCH; ch++) {
            for (int i = tid; i < 4096; i += 128) {
                int o = i >> 6, c = i & 63;
                float v = wfold(ch, o, c);
                __nv_bfloat16 hv = __float2bfloat16_rn(v);
                __nv_bfloat16 lv = __float2bfloat16_rn(v - __bfloat162float(hv));
                uint32_t off = sw128((uint32_t)(o * 128 + c * 2));
                *(__nv_bfloat16*)(sm + OFF_W + ch * 16384 + off) = hv;
                *(__nv_bfloat16*)(sm + OFF_W + ch * 16384 + 8192 + off) = lv;
            }
        }
    }
    if (tid < 64) {
        BV_s[tid] = bg[tid];
        float wc = 0.f;
        if constexpr (V == L_PHI1)  wc = Wg[tid * 2] + Wg[tid * 2 + 1];
        if constexpr (V == L_PHIK1 || V == L_GAMMA1) wc = Wg[tid * CF::CIN];
        WCG_s[tid] = wc;
    }
    for (int i = tid; i < 2048; i += 128) CU_s[i] = 0.f;
    __syncthreads();

    auto rdW = [&](int ch, int o, int c) -> float {
        uint32_t off = sw128((uint32_t)(o * 128 + c * 2));
        float h = __bfloat162float(*(const __nv_bfloat16*)(sm + OFF_W + ch * 16384 + off));
        float l = __bfloat162float(*(const __nv_bfloat16*)(sm + OFF_W + ch * 16384 + 8192 + off));
        return h + l;
    };

    // ---- biasA[o][a] ----
    if constexpr (CF::TRANS || CF::AGG) {
        const float* cusrc = nullptr;
        if constexpr (V == L_PHIK1 || V == L_GAMMAK1) cusrc = g_colU_s;
        if constexpr (V == L_PHI2 || V == L_GAMMA2)   cusrc = g_colU_h;
        constexpr int AGGCH = (V == L_GAMMA1) ? 0 : 1;
        for (int i = tid; i < 2048; i += 128) {
            int o = i >> 5, aa = i & 31;
            int ag = half * 32 + aa;
            float v = 0.f;
            if constexpr (CF::TRANS) {
                #pragma unroll 4
                for (int j = 0; j < 32; j++)
                    v -= rdW(0, o, 32 + j) * cusrc[b * 4096 + (32 + j) * 64 + ag];
            }
            if constexpr (CF::AGG) {
                #pragma unroll 4
                for (int j = 0; j < 32; j++)
                    v += rdW(AGGCH, o, 32 + j) *
                         (g_T[b * 64 + 32 + j] - g_colU_m[b * 4096 + (32 + j) * 64 + ag]);
            }
            BA_s[o * 32 + aa] = v;
        }
    }
    // ---- biasU[o][u] ----
    if constexpr (CF::AGG) {
        constexpr int AGGCH = (V == L_GAMMA1) ? 0 : 1;
        for (int i = tid; i < 4096; i += 128) {
            int o = i >> 6, u = i & 63;
            float v = 0.f;
            #pragma unroll 4
            for (int c = 0; c < 64; c++)
                v -= rdW(AGGCH, o, c) * g_rowA[b * 4096 + c * 64 + u];
            BU_s[o * 64 + u] = v;
        }
    }
    __syncthreads();

    // ---- pipelined loads: step s = t*NCH + ch ----
    auto issue_load = [&](int s) {
        int t = s / ((NCH > 0) ? NCH : 1), ch = (NCH > 0) ? (s % NCH) : 0;
        int buf = s & 1;
        #pragma unroll
        for (int pl = 0; pl < 2; pl++) {
            const __nv_bfloat16* src = pl ? inL[ch] : inH[ch];
            uint32_t dbase = smb + OFF_XB + buf * XBUF_B + pl * 16384;
            #pragma unroll
            for (int j = 0; j < 8; j++) {
                int idx = tid + 128 * j;
                int r = idx >> 3, k = idx & 7;
                int u = t * 4 + (r >> 5);
                int gpos = u * 64 + half * 32 + (r & 31);
                const char* gsrc = (const char*)(src + ((size_t)b * 4096 + gpos) * 64) + k * 16;
                CP_ASYNC16(dbase + sw128((uint32_t)(r * 128 + k * 16)), gsrc);
            }
        }
        CP_COMMIT();
    };

    constexpr int S = (NCH > 0) ? 16 * NCH : 0;
    if constexpr (NCH > 0) issue_load(0);

    float d[2][8][4];
    // ldmatrix lane address components
    const int sel = lane >> 3;
    const int rowoff = ((sel & 1) << 3) | (lane & 7);
    const int koff = (sel >> 1) << 3;
    const int bl_ = lane & 15;
    const int bn = bl_ & 7;
    const int bk = (bl_ >> 3) << 3;

    for (int t = 0; t < 16; t++) {
        if constexpr (NCH > 0) {
            #pragma unroll
            for (int mt = 0; mt < 2; mt++)
                #pragma unroll
                for (int nt = 0; nt < 8; nt++)
                    #pragma unroll
                    for (int q = 0; q < 4; q++) d[mt][nt][q] = 0.f;

            for (int ch = 0; ch < NCH; ch++) {
                const int s = t * NCH + ch;
                if (s + 1 < S) { issue_load(s + 1); CP_WAIT(1); }
                else           { CP_WAIT(0); }
                __syncthreads();

                const uint32_t xbh = smb + OFF_XB + (uint32_t)(s & 1) * XBUF_B;
                const uint32_t xbl = xbh + 16384;
                const uint32_t wbh = smb + OFF_W + ch * 16384;
                const uint32_t wbl = wbh + 8192;

                #pragma unroll
                for (int ks = 0; ks < 4; ks++) {
                    const int k0 = ks * 16;
                    uint32_t ah[2][4], al[2][4];
                    #pragma unroll
                    for (int mt = 0; mt < 2; mt++) {
                        uint32_t ra = sw128((uint32_t)((wid * 32 + mt * 16 + rowoff) * 128 + (k0 + koff) * 2));
                        LDSM4(ah[mt], xbh + ra);
                        LDSM4(al[mt], xbl + ra);
                    }
                    #pragma unroll
                    for (int nt = 0; nt < 8; nt++) {
                        uint32_t rb = sw128((uint32_t)((nt * 8 + bn) * 128 + (k0 + bk) * 2));
                        uint32_t bh0, bh1, bl0, bl1;
                        LDSM2(bh0, bh1, wbh + rb);
                        LDSM2(bl0, bl1, wbl + rb);
                        #pragma unroll
                        for (int mt = 0; mt < 2; mt++) {
                            mma_bf16(d[mt][nt], ah[mt], bh0, bh1);
                            mma_bf16(d[mt][nt], ah[mt], bl0, bl1);
                            mma_bf16(d[mt][nt], al[mt], bh0, bh1);
                        }
                    }
                }
                __syncthreads();   // buffer reuse fence
            }
            // stage D -> STG
            #pragma unroll
            for (int mt = 0; mt < 2; mt++) {
                const int row0 = wid * 32 + mt * 16 + (lane >> 2);
                #pragma unroll
                for (int nt = 0; nt < 8; nt++) {
                    const int col = nt * 8 + (lane & 3) * 2;
                    *(float2*)&STG_s[row0 * STG_STRIDE + col] =
                        make_float2(d[mt][nt][0], d[mt][nt][1]);
                    *(float2*)&STG_s[(row0 + 8) * STG_STRIDE + col] =
                        make_float2(d[mt][nt][2], d[mt][nt][3]);
                }
            }
            __syncthreads();
        }

        // ---- epilogue: thread = one position ----
        const int u = t * 4 + (tid >> 5);
        const int ag = half * 32 + (tid & 31);
        const int gpos = u * 64 + ag;
        float cgv = 0.f;
        if constexpr (CF::CG) cgv = cgp[b * NPOS + gpos];

        float vals[64];
        #pragma unroll
        for (int c = 0; c < 64; c++) {
            float v = (NCH > 0) ? STG_s[tid * STG_STRIDE + c] : 0.f;
            v += BV_s[c];
            if constexpr (CF::TRANS || CF::AGG) v += BA_s[c * 32 + (tid & 31)];
            if constexpr (CF::AGG)              v += BU_s[c * 64 + u];
            if constexpr (CF::CG)               v += WCG_s[c] * cgv;
            if constexpr (CF::RELU)             v = fmaxf(v, 0.f);
            vals[c] = v;
        }
        // pack bf16 hi/lo + store
        {
            uint32_t ph[32], pl[32];
            #pragma unroll
            for (int cc = 0; cc < 32; cc++) {
                float v0 = vals[2 * cc], v1 = vals[2 * cc + 1];
                __nv_bfloat16 h0 = __float2bfloat16_rn(v0);
                __nv_bfloat16 h1 = __float2bfloat16_rn(v1);
                __nv_bfloat16 l0 = __float2bfloat16_rn(v0 - __bfloat162float(h0));
                __nv_bfloat16 l1 = __float2bfloat16_rn(v1 - __bfloat162float(h1));
                __nv_bfloat162 hp; hp.x = h0; hp.y = h1;
                __nv_bfloat162 lp; lp.x = l0; lp.y = l1;
                ph[cc] = *(uint32_t*)&hp;
                pl[cc] = *(uint32_t*)&lp;
            }
            __nv_bfloat16* oh = outH + ((size_t)b * NPOS + gpos) * 64;
            __nv_bfloat16* ol = outL + ((size_t)b * NPOS + gpos) * 64;
            #pragma unroll
            for (int q = 0; q < 8; q++) {
                *(uint4*)(oh + q * 8) = make_uint4(ph[4*q], ph[4*q+1], ph[4*q+2], ph[4*q+3]);
                *(uint4*)(ol + q * 8) = make_uint4(pl[4*q], pl[4*q+1], pl[4*q+2], pl[4*q+3]);
            }
        }
        // write vals back for reductions
        #pragma unroll 8
        for (int c = 0; c < 64; c++) STG_s[tid * STG_STRIDE + c] = vals[c];
        __syncthreads();
        // colU accumulate (in-CTA, no atomics)
        for (int i = tid; i < 2048; i += 128) {
            int o = i >> 5, aa = i & 31;
            float s = STG_s[(0 * 32 + aa) * STG_STRIDE + o] + STG_s[(1 * 32 + aa) * STG_STRIDE + o]
                    + STG_s[(2 * 32 + aa) * STG_STRIDE + o] + STG_s[(3 * 32 + aa) * STG_STRIDE + o];
            CU_s[o * 32 + aa] += s;
        }
        if constexpr (CF::ROWA) {
            for (int i = tid; i < 256; i += 128) {
                int o = i >> 2, ul = i & 3;
                float s = 0.f;
                #pragma unroll 8
                for (int aa = 0; aa < 32; aa++) s += STG_s[(ul * 32 + aa) * STG_STRIDE + o];
                atomicAdd(&g_rowA[b * 4096 + o * 64 + (t * 4 + ul)], s);
            }
        }
        __syncthreads();
    }

    // ---- write colU ----
    for (int i = tid; i < 2048; i += 128) {
        int o = i >> 5, aa = i & 31;
        colUout[b * 4096 + o * 64 + half * 32 + aa] = CU_s[o * 32 + aa];
    }
}

// ---- final layer (1 output channel) ----
__global__ __launch_bounds__(256, 2)
void out5_kernel(const float* __restrict__ W2, const float* __restrict__ b2,
                 float* __restrict__ out)
{
    __shared__ float wf[64], BA[64], b0;
    const int tid = threadIdx.x;
    const int b = blockIdx.y;
    const int pbase = blockIdx.x * 256;
    if (tid < 64) {
        wf[tid] = (tid < 32) ? W2[tid] : -W2[tid] * INV63;
        float v = 0.f;
        #pragma unroll 4
        for (int j = 0; j < 32; j++)
            v += W2[32 + j] * g_colU_h[b * 4096 + (32 + j) * 64 + tid] * INV63;
        BA[tid] = v;
    }
    if (tid == 0) b0 = b2[0];
    __syncthreads();
    const int gpos = pbase + tid;
    const __nv_bfloat16* rh = P_h_hi + ((size_t)b * NPOS + gpos) * 64;
    const __nv_bfloat16* rl = P_h_lo + ((size_t)b * NPOS + gpos) * 64;
    float acc = 0.f;
    #pragma unroll 4
    for (int q = 0; q < 8; q++) {
        uint4 vh = *(const uint4*)(rh + q * 8);
        uint4 vl = *(const uint4*)(rl + q * 8);
        const uint32_t* hw = &vh.x; const uint32_t* lw = &vl.x;
        #pragma unroll
        for (int k = 0; k < 4; k++) {
            __nv_bfloat162 h2 = *(__nv_bfloat162*)&hw[k];
            __nv_bfloat162 l2 = *(__nv_bfloat162*)&lw[k];
            int c = q * 8 + k * 2;
            acc = fmaf(wf[c],     __bfloat162float(h2.x) + __bfloat162float(l2.x), acc);
            acc = fmaf(wf[c + 1], __bfloat162float(h2.y) + __bfloat162float(l2.y), acc);
        }
    }
    out[(size_t)b * NPOS + gpos] = acc + BA[gpos & 63] + b0;
}

__global__ void zero_rowA_kernel()
{
    int i = blockIdx.x * 256 + threadIdx.x;
    if (i < B_ * C_ * U_) g_rowA[i] = 0.f;
}
__global__ void tkernel()
{
    int i = blockIdx.x * blockDim.x + threadIdx.x;
    if (i < B_ * C_) {
        float s = 0.f;
        const float* p = &g_colU_m[i * A_];
        #pragma unroll
        for (int aa = 0; aa < A_; aa++) s += p[aa];
        g_T[i] = s;
    }
}

extern "C" void kernel_launch(void* const* d_in, const int* in_sizes, int n_in,
                              void* d_out, int out_size)
{
    const float* cg        = (const float*)d_in[0];
    const float* phi1_W1   = (const float*)d_in[1];
    const float* phi1_b1   = (const float*)d_in[2];
    const float* phi1_W2   = (const float*)d_in[3];
    const float* phi1_b2   = (const float*)d_in[4];
    const float* phiK_W1   = (const float*)d_in[5];
    const float* phiK_b1   = (const float*)d_in[6];
    const float* phiK_W2   = (const float*)d_in[7];
    const float* phiK_b2   = (const float*)d_in[8];
    const float* gamma1_W1 = (const float*)d_in[9];
    const float* gamma1_b1 = (const float*)d_in[10];
    const float* gamma1_W2 = (const float*)d_in[11];
    const float* gamma1_b2 = (const float*)d_in[12];
    const float* gammaK_W1 = (const float*)d_in[13];
    const float* gammaK_b1 = (const float*)d_in[14];
    const float* gammaK_W2 = (const float*)d_in[15];
    const float* gammaK_b2 = (const float*)d_in[16];
    const float* gamma5_W1 = (const float*)d_in[17];
    const float* gamma5_b1 = (const float*)d_in[18];
    const float* gamma5_W2 = (const float*)d_in[19];
    const float* gamma5_b2 = (const float*)d_in[20];
    float* out = (float*)d_out;

    // dynamic smem opt-in (idempotent; no static guards)
    cudaFuncSetAttribute(layer_kernel<L_PHI1>,    cudaFuncAttributeMaxDynamicSharedMemorySize, smem_bytes(0));
    cudaFuncSetAttribute(layer_kernel<L_PHIK1>,   cudaFuncAttributeMaxDynamicSharedMemorySize, smem_bytes(1));
    cudaFuncSetAttribute(layer_kernel<L_PHI2>,    cudaFuncAttributeMaxDynamicSharedMemorySize, smem_bytes(1));
    cudaFuncSetAttribute(layer_kernel<L_GAMMA1>,  cudaFuncAttributeMaxDynamicSharedMemorySize, smem_bytes(1));
    cudaFuncSetAttribute(layer_kernel<L_GAMMA2>,  cudaFuncAttributeMaxDynamicSharedMemorySize, smem_bytes(1));
    cudaFuncSetAttribute(layer_kernel<L_GAMMAK1>, cudaFuncAttributeMaxDynamicSharedMemorySize, smem_bytes(2));

    dim3 grid(2, B_), blk(128);
    auto phi2 = [&](const float* W, const float* b) {
        zero_rowA_kernel<<<(B_ * C_ * U_ + 255) / 256, 256>>>();
        layer_kernel<L_PHI2><<<grid, blk, smem_bytes(1)>>>(cg, W, b);
        tkernel<<<(B_ * C_ + 127) / 128, 128>>>();
    };

    layer_kernel<L_PHI1><<<grid, blk, smem_bytes(0)>>>(cg, phi1_W1, phi1_b1);
    phi2(phi1_W2, phi1_b2);
    layer_kernel<L_GAMMA1><<<grid, blk, smem_bytes(1)>>>(cg, gamma1_W1, gamma1_b1);
    layer_kernel<L_GAMMA2><<<grid, blk, smem_bytes(1)>>>(cg, gamma1_W2, gamma1_b2);

    for (int i = 0; i < 4; i++) {
        layer_kernel<L_PHIK1><<<grid, blk, smem_bytes(1)>>>(
            cg, phiK_W1 + (size_t)i * 64 * 65, phiK_b1 + i * 64);
        phi2(phiK_W2 + (size_t)i * 64 * 64, phiK_b2 + i * 64);
        if (i < 3) {
            layer_kernel<L_GAMMAK1><<<grid, blk, smem_bytes(2)>>>(
                cg, gammaK_W1 + (size_t)i * 64 * 128, gammaK_b1 + i * 64);
            layer_kernel<L_GAMMA2><<<grid, blk, smem_bytes(1)>>>(
                cg, gammaK_W2 + (size_t)i * 64 * 64, gammaK_b2 + i * 64);
        } else {
            layer_kernel<L_GAMMAK1><<<grid, blk, smem_bytes(2)>>>(
                cg, gamma5_W1, gamma5_b1);
            out5_kernel<<<dim3(16, B_), 256>>>(gamma5_W2, gamma5_b2, out);
        }
    }
}